// round 1
// baseline (speedup 1.0000x reference)
#include <cuda_runtime.h>
#include <math.h>

// ---------------------------------------------------------------------------
// Problem constants
// ---------------------------------------------------------------------------
#define BATCH 4
#define PIX   1024          // H*W = 32*32
#define BC    1024          // balanced channels
#define HEADS 8
#define HD    128           // head dim
#define TOTALC 3072
static const float ATT_SCALE = 0.08838834764831845f;  // 1/sqrt(128)

// ---------------------------------------------------------------------------
// Device scratch (allocation-free: __device__ globals)
// ---------------------------------------------------------------------------
__device__ float g_feat [3ull*BATCH*BC*PIX];   // normalized r,d,l        48MB
__device__ float g_cross[3ull*BATCH*BC*PIX];   // residual sums -> refs   48MB
__device__ float g_q   [(unsigned long long)BATCH*BC*PIX];  // 16MB
__device__ float g_k   [(unsigned long long)BATCH*BC*PIX];
__device__ float g_v   [(unsigned long long)BATCH*BC*PIX];
__device__ float g_att [(unsigned long long)BATCH*BC*PIX];
__device__ float g_spart[8ull*32*HD*HD];       // split-K partial scores  16MB
__device__ float g_attn [32ull*HD*HD];         // softmaxed attention      2MB
__device__ float g_part [3*8*4096*3];          // per-chunk {s,ss,zc}
__device__ float g_inv  [3*4096];              // 1/max(norm,eps) per (mod,b,p)
__device__ float g_metric[3*4096];             // var / zero-frac per (mod,b,p)
__device__ float g_pool [3*BATCH*BC];
__device__ float g_se   [3*BATCH*BC];          // SE sigmoid gates
__device__ float g_gates[3*4096];              // pixel gates per modality
__device__ float g_fused[(unsigned long long)BATCH*TOTALC*PIX];   // 48MB

// ---------------------------------------------------------------------------
// Generic tiled GEMM:  Y[z] (+)= A[z] @ X[z] + bias
//   A: [M,K] row-major (aStride==0 -> shared weights, else batched)
//   X: [K,P] row-major per batch (stride xStride)
//   Y: [M,P] row-major per batch (stride yStride)
// Tiles 128x128, K-step 8, 256 threads, 8x8 per thread.
// M,K,P must be multiples of 128/8/128 respectively (true for all call sites).
// ---------------------------------------------------------------------------
__global__ void __launch_bounds__(256) gemm128(
    const float* __restrict__ A, const float* __restrict__ X,
    const float* __restrict__ bias, float* __restrict__ Y,
    int M, int K, int P,
    long long aStride, long long xStride, long long yStride, int accum)
{
    const int z  = blockIdx.z;
    const float* Ab = A + (long long)z * aStride;
    const float* Xb = X + (long long)z * xStride;
    float*       Yb = Y + (long long)z * yStride;
    const int m0 = blockIdx.y * 128;
    const int p0 = blockIdx.x * 128;

    __shared__ float As[8][128];
    __shared__ float Bs[8][128];

    const int tid = threadIdx.x;
    const int tx = tid & 15;        // 0..15 -> P
    const int ty = tid >> 4;        // 0..15 -> M

    const int a_row = tid >> 1;           // 0..127
    const int a_k4  = (tid & 1) * 4;      // 0 or 4
    const int b_krow = tid >> 5;          // 0..7
    const int b_p4   = (tid & 31) * 4;    // 0..124

    float acc[8][8];
#pragma unroll
    for (int i = 0; i < 8; i++)
#pragma unroll
        for (int j = 0; j < 8; j++) acc[i][j] = 0.f;

    for (int k0 = 0; k0 < K; k0 += 8) {
        float4 av = *(const float4*)&Ab[(long long)(m0 + a_row) * K + k0 + a_k4];
        As[a_k4 + 0][a_row] = av.x;
        As[a_k4 + 1][a_row] = av.y;
        As[a_k4 + 2][a_row] = av.z;
        As[a_k4 + 3][a_row] = av.w;
        float4 bv = *(const float4*)&Xb[(long long)(k0 + b_krow) * P + p0 + b_p4];
        *(float4*)&Bs[b_krow][b_p4] = bv;
        __syncthreads();
#pragma unroll
        for (int kk = 0; kk < 8; kk++) {
            float ar[8], br[8];
            float4 a0 = *(const float4*)&As[kk][ty * 8];
            float4 a1 = *(const float4*)&As[kk][ty * 8 + 4];
            ar[0]=a0.x; ar[1]=a0.y; ar[2]=a0.z; ar[3]=a0.w;
            ar[4]=a1.x; ar[5]=a1.y; ar[6]=a1.z; ar[7]=a1.w;
            float4 b0 = *(const float4*)&Bs[kk][tx * 8];
            float4 b1 = *(const float4*)&Bs[kk][tx * 8 + 4];
            br[0]=b0.x; br[1]=b0.y; br[2]=b0.z; br[3]=b0.w;
            br[4]=b1.x; br[5]=b1.y; br[6]=b1.z; br[7]=b1.w;
#pragma unroll
            for (int i = 0; i < 8; i++)
#pragma unroll
                for (int j = 0; j < 8; j++)
                    acc[i][j] += ar[i] * br[j];
        }
        __syncthreads();
    }

#pragma unroll
    for (int i = 0; i < 8; i++) {
        const int m = m0 + ty * 8 + i;
        const float bval = bias ? bias[m] : 0.f;
#pragma unroll
        for (int j = 0; j < 8; j++) {
            long long idx = (long long)m * P + p0 + tx * 8 + j;
            float v = acc[i][j] + bval;
            if (accum) v += Yb[idx];
            Yb[idx] = v;
        }
    }
}

// ---------------------------------------------------------------------------
// Scores (NT GEMM, split-K over pixels): Spart[split,z] = Qh @ Kh^T (partial)
// grid (8 splits, 1, 32 heads*batch), block 256.
// ---------------------------------------------------------------------------
__global__ void __launch_bounds__(256) scores_nt(
    const float* __restrict__ Qg, const float* __restrict__ Kg,
    float* __restrict__ Spart)
{
    const int z = blockIdx.z;        // b*8+n
    const int split = blockIdx.x;    // 0..7, 128 pixels each
    const float* Qb = Qg + (long long)z * HD * PIX;
    const float* Kb = Kg + (long long)z * HD * PIX;

    __shared__ float Qs[16][128];
    __shared__ float Ks[16][128];

    const int tid = threadIdx.x;
    const int tx = tid & 15, ty = tid >> 4;
    const int r  = tid >> 1;            // channel row 0..127
    const int pq = (tid & 1) * 8;       // 0 or 8 within 16-wide k tile

    float acc[8][8];
#pragma unroll
    for (int i = 0; i < 8; i++)
#pragma unroll
        for (int j = 0; j < 8; j++) acc[i][j] = 0.f;

    for (int t = 0; t < 8; t++) {
        const int pb = split * 128 + t * 16;
        float4 q0 = *(const float4*)&Qb[(long long)r * PIX + pb + pq];
        float4 q1 = *(const float4*)&Qb[(long long)r * PIX + pb + pq + 4];
        Qs[pq+0][r]=q0.x; Qs[pq+1][r]=q0.y; Qs[pq+2][r]=q0.z; Qs[pq+3][r]=q0.w;
        Qs[pq+4][r]=q1.x; Qs[pq+5][r]=q1.y; Qs[pq+6][r]=q1.z; Qs[pq+7][r]=q1.w;
        float4 k0v = *(const float4*)&Kb[(long long)r * PIX + pb + pq];
        float4 k1v = *(const float4*)&Kb[(long long)r * PIX + pb + pq + 4];
        Ks[pq+0][r]=k0v.x; Ks[pq+1][r]=k0v.y; Ks[pq+2][r]=k0v.z; Ks[pq+3][r]=k0v.w;
        Ks[pq+4][r]=k1v.x; Ks[pq+5][r]=k1v.y; Ks[pq+6][r]=k1v.z; Ks[pq+7][r]=k1v.w;
        __syncthreads();
#pragma unroll
        for (int kk = 0; kk < 16; kk++) {
            float ar[8], br[8];
#pragma unroll
            for (int i = 0; i < 8; i++) ar[i] = Qs[kk][ty * 8 + i];
#pragma unroll
            for (int j = 0; j < 8; j++) br[j] = Ks[kk][tx * 8 + j];
#pragma unroll
            for (int i = 0; i < 8; i++)
#pragma unroll
                for (int j = 0; j < 8; j++)
                    acc[i][j] += ar[i] * br[j];
        }
        __syncthreads();
    }

    const long long base = (((long long)split * 32 + z) * HD) * HD;
#pragma unroll
    for (int i = 0; i < 8; i++)
#pragma unroll
        for (int j = 0; j < 8; j++)
            Spart[base + (long long)(ty * 8 + i) * HD + tx * 8 + j] = acc[i][j];
}

// ---------------------------------------------------------------------------
// Softmax over rows of 128, summing the 8 split-K partials first.
// grid (128 rows, 32 zh), block 128.
// ---------------------------------------------------------------------------
__global__ void softmax128(const float* __restrict__ Spart, float* __restrict__ attn)
{
    const int z = blockIdx.y;
    const int h = blockIdx.x;
    const int t = threadIdx.x;
    float s = 0.f;
#pragma unroll
    for (int sp = 0; sp < 8; sp++)
        s += Spart[(((long long)sp * 32 + z) * HD + h) * HD + t];
    s *= ATT_SCALE;

    __shared__ float red[128];
    red[t] = s; __syncthreads();
    for (int o = 64; o > 0; o >>= 1) {
        if (t < o) red[t] = fmaxf(red[t], red[t + o]);
        __syncthreads();
    }
    const float mx = red[0];
    __syncthreads();
    const float e = expf(s - mx);
    red[t] = e; __syncthreads();
    for (int o = 64; o > 0; o >>= 1) {
        if (t < o) red[t] += red[t + o];
        __syncthreads();
    }
    attn[((long long)z * HD + h) * HD + t] = e / red[0];
}

// ---------------------------------------------------------------------------
// Column-wise stats over raw projected features (pre-norm): s, ss, zero-count.
// Deterministic split over channels. grid (16 pix-blocks, 8 ch-chunks, 3 mods).
// ---------------------------------------------------------------------------
__global__ void colreduce(const float* __restrict__ feat, float* __restrict__ part)
{
    const int mod = blockIdx.z, cch = blockIdx.y;
    const int bp = blockIdx.x * 256 + threadIdx.x;   // 0..4095
    const int b = bp >> 10, p = bp & 1023;
    const float* base = feat + (((long long)(mod * BATCH + b) * BC + cch * 128) * PIX) + p;
    float s = 0.f, ss = 0.f, zc = 0.f;
    for (int c = 0; c < 128; c++) {
        float v = base[(long long)c * PIX];
        s += v; ss += v * v;
        zc += (v == 0.0f) ? 1.0f : 0.0f;
    }
    const long long o = (((long long)mod * 8 + cch) * 4096 + bp) * 3;
    part[o] = s; part[o + 1] = ss; part[o + 2] = zc;
}

__global__ void finalize_stats(const float* __restrict__ part,
                               float* __restrict__ inv, float* __restrict__ metric)
{
    const int mod = blockIdx.y;
    const int bp = blockIdx.x * 256 + threadIdx.x;
    float s = 0.f, ss = 0.f, zc = 0.f;
#pragma unroll
    for (int cch = 0; cch < 8; cch++) {
        const long long o = (((long long)mod * 8 + cch) * 4096 + bp) * 3;
        s += part[o]; ss += part[o + 1]; zc += part[o + 2];
    }
    const float norm = sqrtf(ss);
    const float m = fmaxf(norm, 1e-12f);
    const float iv = 1.0f / m;
    inv[mod * 4096 + bp] = iv;
    float met;
    if (mod == 0) {
        const float S = s * iv, SS = ss * iv * iv;
        met = (SS - S * S * (1.0f / 1024.0f)) * (1.0f / 1023.0f);
    } else {
        met = zc * (1.0f / 1024.0f);
    }
    metric[mod * 4096 + bp] = met;
}

// Normalize features in place and seed the residual (cross) buffer.
__global__ void normalize_copy(float* __restrict__ feat, float* __restrict__ cross,
                               const float* __restrict__ inv)
{
    const long long idx = (long long)blockIdx.x * 256 + threadIdx.x;
    const int p = idx & 1023;
    const int mb = (int)(idx >> 20);          // mod*4 + b
    const int mod = mb >> 2, b = mb & 3;
    const float v = feat[idx] * inv[mod * 4096 + b * 1024 + p];
    feat[idx] = v;
    cross[idx] = v;
}

// ---------------------------------------------------------------------------
// SE: pool over pixels, 2-layer MLP, apply
// ---------------------------------------------------------------------------
__global__ void se_pool(const float* __restrict__ cross, float* __restrict__ pool)
{
    const int c = blockIdx.x;          // channel
    const int mb = blockIdx.y;         // mod*4+b
    const float* base = cross + ((long long)mb * BC + c) * PIX;
    float s = 0.f;
    for (int p = threadIdx.x; p < PIX; p += 128) s += base[p];
    __shared__ float red[128];
    red[threadIdx.x] = s; __syncthreads();
    for (int o = 64; o > 0; o >>= 1) {
        if (threadIdx.x < o) red[threadIdx.x] += red[threadIdx.x + o];
        __syncthreads();
    }
    if (threadIdx.x == 0) pool[(long long)mb * BC + c] = red[0] * (1.0f / 1024.0f);
}

__global__ void se_mlp(const float* __restrict__ pool,
                       const float* __restrict__ w1, const float* __restrict__ b1,
                       const float* __restrict__ w2, const float* __restrict__ b2,
                       float* __restrict__ se)
{
    const int mb = blockIdx.x;          // mod*4+b
    const int mod = mb >> 2;
    const int tid = threadIdx.x;
    __shared__ float ps[1024];
    __shared__ float hh[64];
    for (int i = tid; i < 1024; i += 256) ps[i] = pool[(long long)mb * BC + i];
    __syncthreads();
    if (tid < 64) {
        float a = b1[mod * 64 + tid];
        const float* w = w1 + ((long long)mod * 64 + tid) * 1024;
        for (int c = 0; c < 1024; c++) a += w[c] * ps[c];
        hh[tid] = fmaxf(a, 0.f);
    }
    __syncthreads();
#pragma unroll
    for (int q = 0; q < 4; q++) {
        const int c = tid + q * 256;
        float a = b2[mod * 1024 + c];
        const float* w = w2 + ((long long)mod * 1024 + c) * 64;
#pragma unroll
        for (int j = 0; j < 64; j++) a += w[j] * hh[j];
        se[(long long)mb * BC + c] = 1.0f / (1.0f + expf(-a));
    }
}

__global__ void apply_se(float* __restrict__ cross, const float* __restrict__ se)
{
    const long long idx = (long long)blockIdx.x * 256 + threadIdx.x;
    const int c = (int)((idx >> 10) & 1023);
    const int mb = (int)(idx >> 20);
    cross[idx] *= se[(long long)mb * BC + c];
}

// ---------------------------------------------------------------------------
// Pixel gates: sigmoid(gate_w @ [refs, var, dsp, lsp] + gate_b)
// grid 16 blocks x 256 threads, thread per (b,p).
// ---------------------------------------------------------------------------
__global__ void gate_kernel(const float* __restrict__ refs,
                            const float* __restrict__ metric,
                            const float* __restrict__ gw, const float* __restrict__ gb,
                            float* __restrict__ gates)
{
    const int bp = blockIdx.x * 256 + threadIdx.x;
    const int b = bp >> 10, p = bp & 1023;
    float a0 = gb[0], a1 = gb[1], a2 = gb[2];
    for (int mod = 0; mod < 3; mod++) {
        const float* base = refs + ((long long)(mod * BATCH + b) * BC) * PIX + p;
        const float* w0 = gw + 0 * 3075 + mod * 1024;
        const float* w1 = gw + 1 * 3075 + mod * 1024;
        const float* w2 = gw + 2 * 3075 + mod * 1024;
        for (int c = 0; c < 1024; c++) {
            const float v = base[(long long)c * PIX];
            a0 += w0[c] * v; a1 += w1[c] * v; a2 += w2[c] * v;
        }
    }
#pragma unroll
    for (int mod = 0; mod < 3; mod++) {
        const float v = metric[mod * 4096 + bp];
        a0 += gw[0 * 3075 + 3072 + mod] * v;
        a1 += gw[1 * 3075 + 3072 + mod] * v;
        a2 += gw[2 * 3075 + 3072 + mod] * v;
    }
    gates[0 * 4096 + bp] = 1.0f / (1.0f + expf(-a0));
    gates[1 * 4096 + bp] = 1.0f / (1.0f + expf(-a1));
    gates[2 * 4096 + bp] = 1.0f / (1.0f + expf(-a2));
}

// Build fused input: fused[b, mod*1024+c, p] = ref * gate
__global__ void fuse_kernel(const float* __restrict__ refs,
                            const float* __restrict__ gates,
                            float* __restrict__ fused)
{
    const long long idx = (long long)blockIdx.x * 256 + threadIdx.x;
    const int p = idx & 1023;
    const int c = (int)((idx >> 10) & 1023);
    const int mb = (int)(idx >> 20);
    const int mod = mb >> 2, b = mb & 3;
    const float g = gates[mod * 4096 + b * 1024 + p];
    fused[(((long long)b * TOTALC + mod * 1024 + c) * PIX) + p] = refs[idx] * g;
}

// ---------------------------------------------------------------------------
// Host launcher
// ---------------------------------------------------------------------------
extern "C" void kernel_launch(void* const* d_in, const int* in_sizes, int n_in,
                              void* d_out, int out_size)
{
    const float* rgb      = (const float*)d_in[0];
    const float* depth    = (const float*)d_in[1];
    const float* lidar    = (const float*)d_in[2];
    const float* prw      = (const float*)d_in[3];
    const float* prb      = (const float*)d_in[4];
    const float* pdw      = (const float*)d_in[5];
    const float* pdb      = (const float*)d_in[6];
    const float* plw      = (const float*)d_in[7];
    const float* plb      = (const float*)d_in[8];
    const float* aqw      = (const float*)d_in[9];
    const float* aqb      = (const float*)d_in[10];
    const float* akw      = (const float*)d_in[11];
    const float* akb      = (const float*)d_in[12];
    const float* avw      = (const float*)d_in[13];
    const float* avb      = (const float*)d_in[14];
    const float* aow      = (const float*)d_in[15];
    const float* aob      = (const float*)d_in[16];
    const float* sew1     = (const float*)d_in[17];
    const float* seb1     = (const float*)d_in[18];
    const float* sew2     = (const float*)d_in[19];
    const float* seb2     = (const float*)d_in[20];
    const float* gw       = (const float*)d_in[21];
    const float* gb       = (const float*)d_in[22];
    const float* fw       = (const float*)d_in[23];
    const float* fb       = (const float*)d_in[24];
    float* out = (float*)d_out;

    float *feat, *cross, *q, *k, *v, *att, *spart, *attn, *part, *inv, *metric,
          *pool, *se, *gates, *fused;
    cudaGetSymbolAddress((void**)&feat,  g_feat);
    cudaGetSymbolAddress((void**)&cross, g_cross);
    cudaGetSymbolAddress((void**)&q,     g_q);
    cudaGetSymbolAddress((void**)&k,     g_k);
    cudaGetSymbolAddress((void**)&v,     g_v);
    cudaGetSymbolAddress((void**)&att,   g_att);
    cudaGetSymbolAddress((void**)&spart, g_spart);
    cudaGetSymbolAddress((void**)&attn,  g_attn);
    cudaGetSymbolAddress((void**)&part,  g_part);
    cudaGetSymbolAddress((void**)&inv,   g_inv);
    cudaGetSymbolAddress((void**)&metric,g_metric);
    cudaGetSymbolAddress((void**)&pool,  g_pool);
    cudaGetSymbolAddress((void**)&se,    g_se);
    cudaGetSymbolAddress((void**)&gates, g_gates);
    cudaGetSymbolAddress((void**)&fused, g_fused);

    const long long fmodStride = (long long)BATCH * BC * PIX;   // per-modality in feat/cross

    // --- 1. Projections (raw, pre-norm) ---
    gemm128<<<dim3(8, 8, BATCH), 256>>>(prw, rgb,   prb, feat + 0 * fmodStride,
        BC, 512, PIX, 0, 512LL * PIX, (long long)BC * PIX, 0);
    gemm128<<<dim3(8, 8, BATCH), 256>>>(pdw, depth, pdb, feat + 1 * fmodStride,
        BC, 256, PIX, 0, 256LL * PIX, (long long)BC * PIX, 0);
    gemm128<<<dim3(8, 8, BATCH), 256>>>(plw, lidar, plb, feat + 2 * fmodStride,
        BC, 64, PIX, 0, 64LL * PIX, (long long)BC * PIX, 0);

    // --- 2. Stats + normalization (+ seed cross with normalized features) ---
    colreduce<<<dim3(16, 8, 3), 256>>>(feat, part);
    finalize_stats<<<dim3(16, 3), 256>>>(part, inv, metric);
    normalize_copy<<<49152, 256>>>(feat, cross, inv);

    // --- 3. Six cross-attention blocks ---
    const int qmod[6] = {0, 0, 1, 1, 2, 2};
    const int kmod[6] = {1, 2, 0, 2, 0, 1};
    for (int i = 0; i < 6; i++) {
        const float* qf  = feat + (long long)qmod[i] * fmodStride;
        const float* kvf = feat + (long long)kmod[i] * fmodStride;
        const long long wOff = (long long)i * BC * BC;
        const long long bOff = (long long)i * BC;
        // Q, K, V projections
        gemm128<<<dim3(8, 8, BATCH), 256>>>(aqw + wOff, qf,  aqb + bOff, q,
            BC, BC, PIX, 0, (long long)BC * PIX, (long long)BC * PIX, 0);
        gemm128<<<dim3(8, 8, BATCH), 256>>>(akw + wOff, kvf, akb + bOff, k,
            BC, BC, PIX, 0, (long long)BC * PIX, (long long)BC * PIX, 0);
        gemm128<<<dim3(8, 8, BATCH), 256>>>(avw + wOff, kvf, avb + bOff, v,
            BC, BC, PIX, 0, (long long)BC * PIX, (long long)BC * PIX, 0);
        // scores (split-K) + softmax
        scores_nt<<<dim3(8, 1, 32), 256>>>(q, k, spart);
        softmax128<<<dim3(128, 32), 128>>>(spart, attn);
        // attn @ V  (batched A, one z per (b, head))
        gemm128<<<dim3(8, 1, 32), 256>>>(attn, v, nullptr, att,
            HD, HD, PIX, (long long)HD * HD, (long long)HD * PIX, (long long)HD * PIX, 0);
        // output projection, accumulate into cross[qmod]
        gemm128<<<dim3(8, 8, BATCH), 256>>>(aow + wOff, att, aob + bOff,
            cross + (long long)qmod[i] * fmodStride,
            BC, BC, PIX, 0, (long long)BC * PIX, (long long)BC * PIX, 1);
    }

    // --- 4. SE gating (cross -> refs in place) ---
    se_pool<<<dim3(1024, 12), 128>>>(cross, pool);
    se_mlp<<<12, 256>>>(pool, sew1, seb1, sew2, seb2, se);
    apply_se<<<49152, 256>>>(cross, se);

    // --- 5. Pixel gates ---
    gate_kernel<<<16, 256>>>(cross, metric, gw, gb, gates);

    // --- 6. Fused input + final fusion GEMM -> d_out ---
    fuse_kernel<<<49152, 256>>>(cross, gates, fused);
    gemm128<<<dim3(8, 24, BATCH), 256>>>(fw, fused, fb, out,
        TOTALC, TOTALC, PIX, 0, (long long)TOTALC * PIX, (long long)TOTALC * PIX, 0);
}